// round 14
// baseline (speedup 1.0000x reference)
#include <cuda_runtime.h>
#include <math.h>

// B=32, T=512, F=1280, H=512, L=3. 3H=1536, 2H=1024. M=B*T=16384.
//
// NOTE (R11): harness builds via compute_103 PTX => NO tcgen05. FFMA2 path.
//
// Layouts:
//   xg   [dir][t*32+b][1536]        (input projections, gate-major r/z/n)
//   y    [dir][t][c][b] (512x512x32) transposed hidden outputs
//   xin  [b*512+t][1024]            next-layer input / final output layout
//
// Launch order per layer: zero_a, zero_b, bar_init, gemm(#4 = ncu ordinal),
// gru, stats, finalize, apply.

#define XG_DIR 25165824   // 512*32*1536
#define Y_DIR   8388608   // 512*512*32

typedef unsigned long long u64;

#define FFMA2(c, a, b) asm("fma.rn.f32x2 %0, %1, %2, %0;" : "+l"(c) : "l"(a), "l"(b))

__device__ __forceinline__ u64 pk(float x) {
    u64 r; unsigned u = __float_as_uint(x);
    asm("mov.b64 %0, {%1, %1};" : "=l"(r) : "r"(u));
    return r;
}
__device__ __forceinline__ float f2lo(u64 v) { return __uint_as_float((unsigned)v); }
__device__ __forceinline__ float f2hi(u64 v) { return __uint_as_float((unsigned)(v >> 32)); }

// ---------------- scratch (device globals; no allocation allowed) ----------
__device__ float g_xg[2 * XG_DIR];        // 201 MB
__device__ float g_y [2 * Y_DIR];         //  67 MB
__device__ float g_xin[32 * 512 * 1024];  //  67 MB
__device__ float g_scale[1024];
__device__ float g_shift[1024];
__device__ float g_sum[1024];
__device__ float g_sqs[1024];
__device__ unsigned g_cnt[64];            // arrival counters: [dir*32] used
__device__ volatile unsigned g_relp[64];  // release words:    [dir*32] used

// ---------------------------------------------------------------------------
// GEMM: A[16384][K] * W[3072][K]^T + bias -> g_xg  (scatter [dir][t*32+b][g])
// 128(M) x 256(N) block tile, BK=8, DOUBLE-BUFFERED smem (1 sync per tile).
// Thread: 8 rows x 16 cols as 8x8 packed f32x2.
// ---------------------------------------------------------------------------
__global__ __launch_bounds__(256) void gemm_xg(
    const float* __restrict__ Ap,     // nullptr -> g_xin
    const float* __restrict__ W,      // [3072][K]
    const float* __restrict__ bias,   // [3072]
    int K)
{
    const float* A = Ap ? Ap : g_xin;
    __shared__ float As[2][8][128];
    __shared__ float Bs[2][8][256];

    const int tid = threadIdx.x;
    const int bn = blockIdx.x;        // 0..11
    const int bm = blockIdx.y;        // 0..127
    const int lr = tid >> 1;
    const int lk = (tid & 1) << 2;

    const float* Ag = A + (size_t)(bm * 128 + lr) * K + lk;
    const float* Wg = W + (size_t)(bn * 256 + tid) * K;

    float4 av  = *(const float4*)Ag;
    float4 bv0 = *(const float4*)Wg;
    float4 bv1 = *(const float4*)(Wg + 4);

    const int tx = tid & 15;
    const int ty = tid >> 4;

    u64 acc[8][8];
#pragma unroll
    for (int i = 0; i < 8; i++)
#pragma unroll
        for (int j = 0; j < 8; j++) acc[i][j] = 0ull;

    // stage tile 0 into buffer 0
    As[0][lk + 0][lr] = av.x; As[0][lk + 1][lr] = av.y;
    As[0][lk + 2][lr] = av.z; As[0][lk + 3][lr] = av.w;
    Bs[0][0][tid] = bv0.x; Bs[0][1][tid] = bv0.y; Bs[0][2][tid] = bv0.z; Bs[0][3][tid] = bv0.w;
    Bs[0][4][tid] = bv1.x; Bs[0][5][tid] = bv1.y; Bs[0][6][tid] = bv1.z; Bs[0][7][tid] = bv1.w;
    __syncthreads();

    int p = 0;
    for (int kt = 0; kt < K; kt += 8) {
        const bool more = (kt + 8 < K);
        if (more) {                            // global prefetch of next tile
            av  = *(const float4*)(Ag + kt + 8);
            bv0 = *(const float4*)(Wg + kt + 8);
            bv1 = *(const float4*)(Wg + kt + 12);
        }

#pragma unroll
        for (int k = 0; k < 8; k++) {
            float4 a0 = *(const float4*)&As[p][k][4 * ty];
            float4 a1 = *(const float4*)&As[p][k][64 + 4 * ty];
            u64 ap0 = pk(a0.x), ap1 = pk(a0.y), ap2 = pk(a0.z), ap3 = pk(a0.w);
            u64 ap4 = pk(a1.x), ap5 = pk(a1.y), ap6 = pk(a1.z), ap7 = pk(a1.w);
            ulonglong2 bq0 = *(const ulonglong2*)&Bs[p][k][4 * tx];
            ulonglong2 bq1 = *(const ulonglong2*)&Bs[p][k][64 + 4 * tx];
            ulonglong2 bq2 = *(const ulonglong2*)&Bs[p][k][128 + 4 * tx];
            ulonglong2 bq3 = *(const ulonglong2*)&Bs[p][k][192 + 4 * tx];
#define ROWFMA(i, ap)                                                   \
            FFMA2(acc[i][0], ap, bq0.x); FFMA2(acc[i][1], ap, bq0.y);   \
            FFMA2(acc[i][2], ap, bq1.x); FFMA2(acc[i][3], ap, bq1.y);   \
            FFMA2(acc[i][4], ap, bq2.x); FFMA2(acc[i][5], ap, bq2.y);   \
            FFMA2(acc[i][6], ap, bq3.x); FFMA2(acc[i][7], ap, bq3.y);
            ROWFMA(0, ap0) ROWFMA(1, ap1) ROWFMA(2, ap2) ROWFMA(3, ap3)
            ROWFMA(4, ap4) ROWFMA(5, ap5) ROWFMA(6, ap6) ROWFMA(7, ap7)
#undef ROWFMA
        }

        if (more) {                            // store into other buffer
            const int q = p ^ 1;
            As[q][lk + 0][lr] = av.x; As[q][lk + 1][lr] = av.y;
            As[q][lk + 2][lr] = av.z; As[q][lk + 3][lr] = av.w;
            Bs[q][0][tid] = bv0.x; Bs[q][1][tid] = bv0.y;
            Bs[q][2][tid] = bv0.z; Bs[q][3][tid] = bv0.w;
            Bs[q][4][tid] = bv1.x; Bs[q][5][tid] = bv1.y;
            Bs[q][6][tid] = bv1.z; Bs[q][7][tid] = bv1.w;
            __syncthreads();
            p = q;
        }
    }

    const int nb  = bn * 256;
    const int dir = (bn >= 6);
    const int gb  = nb - dir * 1536 + 4 * tx;
    float4 bq[4];
#pragma unroll
    for (int q = 0; q < 4; q++)
        bq[q] = *(const float4*)(bias + nb + 64 * q + 4 * tx);
    float* xg = g_xg + dir * XG_DIR;

#pragma unroll
    for (int i = 0; i < 8; i++) {
        int row = (i < 4) ? (4 * ty + i) : (64 + 4 * ty + (i - 4));
        int m = bm * 128 + row;
        int b = m >> 9, t = m & 511;
        float* rp = xg + (t * 32 + b) * 1536 + gb;
#pragma unroll
        for (int q = 0; q < 4; q++) {
            float4 v;
            v.x = f2lo(acc[i][2 * q])     + bq[q].x;
            v.y = f2hi(acc[i][2 * q])     + bq[q].y;
            v.z = f2lo(acc[i][2 * q + 1]) + bq[q].z;
            v.w = f2hi(acc[i][2 * q + 1]) + bq[q].w;
            *(float4*)(rp + 64 * q) = v;
        }
    }
}

// ---------------------------------------------------------------------------
// Recurrence (R13 known-good): 128 CTAs x 512 threads. CTA = (dir, 8 cols).
// Grid barrier: atomicAdd arrival + last-arriver release (padded lines).
// smem floats: Ws[24][520] | Hs[512][32] | Red[24][264] | Bh[24]
// ---------------------------------------------------------------------------
#define REC_SMEM_FLOATS 35232
#define REC_SMEM_BYTES  (REC_SMEM_FLOATS * 4)
#define WS_OFF  0
#define HS_OFF  12480
#define RED_OFF 28864
#define BH_OFF  35200

__global__ __launch_bounds__(512, 1) void gru_rec(
    const float* __restrict__ whh,    // [2][1536][512]
    const float* __restrict__ bhh)    // [2][1536]
{
    extern __shared__ float sm[];
    float* Ws  = sm + WS_OFF;         // [24][520] padded rows
    float* Hs  = sm + HS_OFF;         // [512][32] h_prev, k-major
    float* Red = sm + RED_OFF;        // [24][264] padded
    float* Bh  = sm + BH_OFF;         // [24]

    const int tid = threadIdx.x;
    const int dir = blockIdx.x >> 6;
    const int cb  = blockIdx.x & 63;

    const float* wbase = whh + dir * (1536 * 512);
#pragma unroll
    for (int i = 0; i < 6; i++) {
        int idx4 = tid + i * 512;           // 0..3071 (float4 index)
        int row  = idx4 >> 7;               // 0..23  (g*8 + cl)
        int k4   = idx4 & 127;
        int g = row >> 3, cl = row & 7;
        float4 v = *(const float4*)(wbase + ((g << 9) + cb * 8 + cl) * 512 + k4 * 4);
        *(float4*)(Ws + row * 520 + k4 * 4) = v;
    }
    if (tid < 24) {
        int g = tid >> 3, cl = tid & 7;
        Bh[tid] = bhh[dir * 1536 + (g << 9) + cb * 8 + cl];
    }
    __syncthreads();

    const int ks = tid >> 6;            // 0..7  k-eighth (phase 1)
    const int rr = tid & 63;
    const int c  = rr >> 3;             // 0..7  column
    const int bg = rr & 7;              // 0..7  batch quad
    const int k0 = ks << 6;

    const int c2 = tid >> 5;            // 0..7  (phase 2, tid<256)
    const int b2 = tid & 31;

    const float* xgb = g_xg + dir * XG_DIR;
    float*       yb  = g_y  + dir * Y_DIR;

    const float* w0 = Ws + (0 * 8 + c) * 520 + k0;    // r gate row
    const float* w1 = Ws + (1 * 8 + c) * 520 + k0;    // z gate row
    const float* w2 = Ws + (2 * 8 + c) * 520 + k0;    // n gate row
    const float* hb = Hs + (k0 << 5) + (bg << 2);

    float bhr = 0.f, bhz = 0.f, bhn = 0.f;
    if (tid < 256) {
        bhr = Bh[c2]; bhz = Bh[8 + c2]; bhn = Bh[16 + c2];
    }

    for (int step = 0; step < 512; step++) {
        const int tt = dir ? (511 - step) : step;
        const int tp = dir ? (tt + 1) : (tt - 1);
        const float* hsrc = yb + tp * 16384;

        // xg prefetch for phase 2 (hidden under staging + phase 1)
        float xr = 0.f, xz = 0.f, xn = 0.f;
        if (tid < 256) {
            const float* xp = xgb + (tt * 32 + b2) * 1536 + cb * 8 + c2;
            xr = __ldg(xp); xz = __ldg(xp + 512); xn = __ldg(xp + 1024);
        }

        // stage h_prev into Hs (contiguous 64KB, coalesced)
        if (step == 0) {
#pragma unroll
            for (int i = 0; i < 8; i++)
                *(float4*)(Hs + ((tid + i * 512) << 2)) = make_float4(0.f, 0.f, 0.f, 0.f);
        } else {
#pragma unroll
            for (int i = 0; i < 8; i++) {
                int idx = (tid + i * 512) << 2;
                *(float4*)(Hs + idx) = __ldcg((const float4*)(hsrc + idx));
            }
        }
        __syncthreads();

        // phase 1: 3 gates x 2 batch-pairs over 64 k
        u64 a0x = 0ull, a0y = 0ull, a1x = 0ull, a1y = 0ull, a2x = 0ull, a2y = 0ull;
#pragma unroll 4
        for (int kk = 0; kk < 64; kk += 4) {
            ulonglong2 h0 = *(const ulonglong2*)(hb + ((kk + 0) << 5));
            ulonglong2 h1 = *(const ulonglong2*)(hb + ((kk + 1) << 5));
            ulonglong2 h2 = *(const ulonglong2*)(hb + ((kk + 2) << 5));
            ulonglong2 h3 = *(const ulonglong2*)(hb + ((kk + 3) << 5));
            float4 wr = *(const float4*)(w0 + kk);
            float4 wz = *(const float4*)(w1 + kk);
            float4 wn = *(const float4*)(w2 + kk);
            u64 p;
            p = pk(wr.x); FFMA2(a0x, h0.x, p); FFMA2(a0y, h0.y, p);
            p = pk(wr.y); FFMA2(a0x, h1.x, p); FFMA2(a0y, h1.y, p);
            p = pk(wr.z); FFMA2(a0x, h2.x, p); FFMA2(a0y, h2.y, p);
            p = pk(wr.w); FFMA2(a0x, h3.x, p); FFMA2(a0y, h3.y, p);
            p = pk(wz.x); FFMA2(a1x, h0.x, p); FFMA2(a1y, h0.y, p);
            p = pk(wz.y); FFMA2(a1x, h1.x, p); FFMA2(a1y, h1.y, p);
            p = pk(wz.z); FFMA2(a1x, h2.x, p); FFMA2(a1y, h2.y, p);
            p = pk(wz.w); FFMA2(a1x, h3.x, p); FFMA2(a1y, h3.y, p);
            p = pk(wn.x); FFMA2(a2x, h0.x, p); FFMA2(a2y, h0.y, p);
            p = pk(wn.y); FFMA2(a2x, h1.x, p); FFMA2(a2y, h1.y, p);
            p = pk(wn.z); FFMA2(a2x, h2.x, p); FFMA2(a2y, h2.y, p);
            p = pk(wn.w); FFMA2(a2x, h3.x, p); FFMA2(a2y, h3.y, p);
        }

        // store partials: Red[(g*8 + c)][ks*32 + 4bg + {0..3}]
        {
            float* rp0 = Red + (0 * 8 + c) * 264 + (ks << 5) + (bg << 2);
            float* rp1 = Red + (1 * 8 + c) * 264 + (ks << 5) + (bg << 2);
            float* rp2 = Red + (2 * 8 + c) * 264 + (ks << 5) + (bg << 2);
            *(u64*)(rp0) = a0x; *(u64*)(rp0 + 2) = a0y;
            *(u64*)(rp1) = a1x; *(u64*)(rp1 + 2) = a1y;
            *(u64*)(rp2) = a2x; *(u64*)(rp2 + 2) = a2y;
        }
        __syncthreads();

        // phase 2: thread (c2, b2) reduces 8 k-partials and applies gates
        if (tid < 256) {
            float s[3];
#pragma unroll
            for (int g = 0; g < 3; g++) {
                const float* rp = Red + ((g << 3) + c2) * 264 + b2;
                float t0 = rp[0]   + rp[32],  t1 = rp[64]  + rp[96];
                float t2 = rp[128] + rp[160], t3 = rp[192] + rp[224];
                s[g] = (t0 + t1) + (t2 + t3);
            }
            const float hp = Hs[(((cb << 3) + c2) << 5) + b2];   // 0 at step 0
            const float r = 1.f / (1.f + expf(-(xr + s[0] + bhr)));
            const float z = 1.f / (1.f + expf(-(xz + s[1] + bhz)));
            const float n = tanhf(xn + r * (s[2] + bhn));
            yb[tt * 16384 + (((cb << 3) + c2) << 5) + b2] = (1.f - z) * n + z * hp;
        }

        // ---- grid barrier: atomic arrival + last-arriver release ----
        __syncthreads();                         // all y stores issued
        const unsigned tgt = (unsigned)step + 1u;
        if (tid == 0) {
            __threadfence();                     // y visible before arrival
            unsigned old = atomicAdd(&g_cnt[dir * 32], 1u);
            if (old == ((unsigned)step << 6) + 63u) {
                g_relp[dir * 32] = tgt;          // completer releases directly
            } else {
                while ((int)(g_relp[dir * 32] - tgt) < 0) { }
            }
            __threadfence();                     // acquire
        }
        __syncthreads();
    }
}

// ---------------------------------------------------------------------------
// BatchNorm (training-mode batch stats), folded to scale/shift
// ---------------------------------------------------------------------------
__global__ void bn_zero_a() { g_sum[threadIdx.x] = 0.f; }   // 1024 threads
__global__ void bn_zero_b() { g_sqs[threadIdx.x] = 0.f; }   // 1024 threads

__global__ void bar_init()
{
    int t = threadIdx.x;                      // 64 threads
    g_cnt[t] = 0u;
    g_relp[t] = 0u;
}

__global__ __launch_bounds__(256) void bn_stats()
{
    const int ch = blockIdx.x;
    const int dir = ch >> 9, c = ch & 511;
    const float* p = g_y + dir * Y_DIR + c * 32;
    float s = 0.f, q = 0.f;
#pragma unroll 4
    for (int i = threadIdx.x; i < 512 * 32; i += 256) {
        int t = i >> 5, b = i & 31;
        float v = p[t * 16384 + b];
        s += v; q += v * v;
    }
#pragma unroll
    for (int o = 16; o > 0; o >>= 1) {
        s += __shfl_down_sync(0xFFFFFFFFu, s, o);
        q += __shfl_down_sync(0xFFFFFFFFu, q, o);
    }
    if ((threadIdx.x & 31) == 0) {
        atomicAdd(&g_sum[ch], s);
        atomicAdd(&g_sqs[ch], q);
    }
}

__global__ void bn_finalize(const float* __restrict__ gamma,
                            const float* __restrict__ beta)
{
    int c = threadIdx.x;                      // 1024 threads
    float mean = g_sum[c] * (1.f / 16384.f);
    float var  = g_sqs[c] * (1.f / 16384.f) - mean * mean;
    float sc   = gamma[c] * rsqrtf(var + 1e-5f);
    g_scale[c] = sc;
    g_shift[c] = beta[c] - mean * sc;
}

__global__ __launch_bounds__(256) void bn_apply(float* __restrict__ out, int last)
{
    __shared__ float tile[256 * 33];
    const int bi   = blockIdx.x;              // t(512) x dir(2) x half(2)
    const int t    = bi >> 2;
    const int dir  = (bi >> 1) & 1;
    const int half = bi & 1;

    const float* src = g_y + dir * Y_DIR + t * 16384 + half * 256 * 32;
    for (int i = threadIdx.x; i < 8192; i += 256) {
        int c = i >> 5, b = i & 31;
        tile[c * 33 + b] = src[c * 32 + b];
    }
    __syncthreads();

    float* dst = last ? out : g_xin;
    const int chb = dir * 512 + half * 256;
    for (int i = threadIdx.x; i < 8192; i += 256) {
        int b = i >> 8, c = i & 255;
        int ch = chb + c;
        dst[(size_t)(b * 512 + t) * 1024 + ch] =
            tile[c * 33 + b] * g_scale[ch] + g_shift[ch];
    }
}

// ---------------------------------------------------------------------------
extern "C" void kernel_launch(void* const* d_in, const int* in_sizes, int n_in,
                              void* d_out, int out_size)
{
    const float* x         = (const float*)d_in[0];   // [32][512][1280]
    const float* w_ih0     = (const float*)d_in[1];   // [2][1536][1280]
    const float* w_hh0     = (const float*)d_in[2];   // [2][1536][512]
    const float* b_ih0     = (const float*)d_in[3];   // [2][1536]
    const float* b_hh0     = (const float*)d_in[4];   // [2][1536]
    const float* w_ih_rest = (const float*)d_in[5];   // [2][2][1536][1024]
    const float* w_hh_rest = (const float*)d_in[6];   // [2][2][1536][512]
    const float* b_ih_rest = (const float*)d_in[7];   // [2][2][1536]
    const float* b_hh_rest = (const float*)d_in[8];   // [2][2][1536]
    const float* gamma     = (const float*)d_in[9];   // [3][1024]
    const float* beta      = (const float*)d_in[10];  // [3][1024]
    float* out = (float*)d_out;                       // [32][512][1024]

    static int attr_set = 0;
    if (!attr_set) {
        cudaFuncSetAttribute(gru_rec, cudaFuncAttributeMaxDynamicSharedMemorySize,
                             REC_SMEM_BYTES);
        attr_set = 1;
    }

    for (int l = 0; l < 3; l++) {
        const float* A   = (l == 0) ? x : nullptr;    // nullptr -> g_xin
        const int    K   = (l == 0) ? 1280 : 1024;
        const float* Wih = (l == 0) ? w_ih0 : w_ih_rest + (size_t)(l - 1) * 2 * 1536 * 1024;
        const float* Bih = (l == 0) ? b_ih0 : b_ih_rest + (l - 1) * 3072;
        const float* Whh = (l == 0) ? w_hh0 : w_hh_rest + (size_t)(l - 1) * 2 * 1536 * 512;
        const float* Bhh = (l == 0) ? b_hh0 : b_hh_rest + (l - 1) * 3072;

        bn_zero_a<<<1, 1024>>>();
        bn_zero_b<<<1, 1024>>>();
        bar_init<<<1, 64>>>();
        gemm_xg<<<dim3(12, 128), 256>>>(A, Wih, Bih, K);      // ncu ordinal #4
        gru_rec<<<128, 512, REC_SMEM_BYTES>>>(Whh, Bhh);
        bn_stats<<<1024, 256>>>();
        bn_finalize<<<1, 1024>>>(gamma + l * 1024, beta + l * 1024);
        bn_apply<<<2048, 256>>>(out, (l == 2) ? 1 : 0);
    }
}

// round 15
// speedup vs baseline: 1.1123x; 1.1123x over previous
#include <cuda_runtime.h>
#include <math.h>

// B=32, T=512, F=1280, H=512, L=3. 3H=1536, 2H=1024. M=B*T=16384.
//
// NOTE (R11): harness builds via compute_103 PTX => NO tcgen05. FFMA2 path.
// NOTE (R14): GEMM double-buffering regresses (ptxas sinks prefetch loads);
//             single-buffer 2-sync version is the known optimum (fma=66.8%).
//
// Layouts:
//   xg   [dir][t*32+b][1536]        (input projections, gate-major r/z/n)
//   y    [dir][t][c][b] (512x512x32) transposed hidden outputs
//   xin  [b*512+t][1024]            next-layer input / final output layout
//
// Launch order per layer: zero, bar_init, gemm, gru(#4 = ncu ordinal),
// stats, finalize, apply.

#define XG_DIR 25165824   // 512*32*1536
#define Y_DIR   8388608   // 512*512*32

typedef unsigned long long u64;

#define FFMA2(c, a, b) asm("fma.rn.f32x2 %0, %1, %2, %0;" : "+l"(c) : "l"(a), "l"(b))

__device__ __forceinline__ u64 pk(float x) {
    u64 r; unsigned u = __float_as_uint(x);
    asm("mov.b64 %0, {%1, %1};" : "=l"(r) : "r"(u));
    return r;
}
__device__ __forceinline__ float f2lo(u64 v) { return __uint_as_float((unsigned)v); }
__device__ __forceinline__ float f2hi(u64 v) { return __uint_as_float((unsigned)(v >> 32)); }

// ---------------- scratch (device globals; no allocation allowed) ----------
__device__ float g_xg[2 * XG_DIR];        // 201 MB
__device__ float g_y [2 * Y_DIR];         //  67 MB
__device__ float g_xin[32 * 512 * 1024];  //  67 MB
__device__ float g_scale[1024];
__device__ float g_shift[1024];
__device__ float g_sum[1024];
__device__ float g_sqs[1024];
__device__ unsigned g_cnt[64];            // arrival counters: [dir*32] used
__device__ volatile unsigned g_relp[64];  // release words:    [dir*32] used

// ---------------------------------------------------------------------------
// GEMM (R13 known-good, fma=66.8%): A[16384][K] * W[3072][K]^T + bias -> g_xg
// 128(M) x 256(N) block tile, BK=8. Thread: 8 rows x 16 cols (8 f32x2 pairs).
// ---------------------------------------------------------------------------
__global__ __launch_bounds__(256) void gemm_xg(
    const float* __restrict__ Ap,     // nullptr -> g_xin
    const float* __restrict__ W,      // [3072][K]
    const float* __restrict__ bias,   // [3072]
    int K)
{
    const float* A = Ap ? Ap : g_xin;
    __shared__ float As[8][128];
    __shared__ float Bs[8][256];

    const int tid = threadIdx.x;
    const int bn = blockIdx.x;        // 0..11
    const int bm = blockIdx.y;        // 0..127
    const int lr = tid >> 1;
    const int lk = (tid & 1) << 2;

    const float* Ag = A + (size_t)(bm * 128 + lr) * K + lk;
    const float* Wg = W + (size_t)(bn * 256 + tid) * K;

    float4 av  = *(const float4*)Ag;
    float4 bv0 = *(const float4*)Wg;
    float4 bv1 = *(const float4*)(Wg + 4);

    const int tx = tid & 15;
    const int ty = tid >> 4;

    u64 acc[8][8];
#pragma unroll
    for (int i = 0; i < 8; i++)
#pragma unroll
        for (int j = 0; j < 8; j++) acc[i][j] = 0ull;

    for (int kt = 0; kt < K; kt += 8) {
        As[lk + 0][lr] = av.x; As[lk + 1][lr] = av.y;
        As[lk + 2][lr] = av.z; As[lk + 3][lr] = av.w;
        Bs[0][tid] = bv0.x; Bs[1][tid] = bv0.y; Bs[2][tid] = bv0.z; Bs[3][tid] = bv0.w;
        Bs[4][tid] = bv1.x; Bs[5][tid] = bv1.y; Bs[6][tid] = bv1.z; Bs[7][tid] = bv1.w;
        __syncthreads();

        if (kt + 8 < K) {
            av  = *(const float4*)(Ag + kt + 8);
            bv0 = *(const float4*)(Wg + kt + 8);
            bv1 = *(const float4*)(Wg + kt + 12);
        }

#pragma unroll
        for (int k = 0; k < 8; k++) {
            float4 a0 = *(const float4*)&As[k][4 * ty];
            float4 a1 = *(const float4*)&As[k][64 + 4 * ty];
            u64 ap0 = pk(a0.x), ap1 = pk(a0.y), ap2 = pk(a0.z), ap3 = pk(a0.w);
            u64 ap4 = pk(a1.x), ap5 = pk(a1.y), ap6 = pk(a1.z), ap7 = pk(a1.w);
            ulonglong2 bq0 = *(const ulonglong2*)&Bs[k][4 * tx];
            ulonglong2 bq1 = *(const ulonglong2*)&Bs[k][64 + 4 * tx];
            ulonglong2 bq2 = *(const ulonglong2*)&Bs[k][128 + 4 * tx];
            ulonglong2 bq3 = *(const ulonglong2*)&Bs[k][192 + 4 * tx];
#define ROWFMA(i, ap)                                                   \
            FFMA2(acc[i][0], ap, bq0.x); FFMA2(acc[i][1], ap, bq0.y);   \
            FFMA2(acc[i][2], ap, bq1.x); FFMA2(acc[i][3], ap, bq1.y);   \
            FFMA2(acc[i][4], ap, bq2.x); FFMA2(acc[i][5], ap, bq2.y);   \
            FFMA2(acc[i][6], ap, bq3.x); FFMA2(acc[i][7], ap, bq3.y);
            ROWFMA(0, ap0) ROWFMA(1, ap1) ROWFMA(2, ap2) ROWFMA(3, ap3)
            ROWFMA(4, ap4) ROWFMA(5, ap5) ROWFMA(6, ap6) ROWFMA(7, ap7)
#undef ROWFMA
        }
        __syncthreads();
    }

    const int nb  = bn * 256;
    const int dir = (bn >= 6);
    const int gb  = nb - dir * 1536 + 4 * tx;
    float4 bq[4];
#pragma unroll
    for (int q = 0; q < 4; q++)
        bq[q] = *(const float4*)(bias + nb + 64 * q + 4 * tx);
    float* xg = g_xg + dir * XG_DIR;

#pragma unroll
    for (int i = 0; i < 8; i++) {
        int row = (i < 4) ? (4 * ty + i) : (64 + 4 * ty + (i - 4));
        int m = bm * 128 + row;
        int b = m >> 9, t = m & 511;
        float* rp = xg + (t * 32 + b) * 1536 + gb;
#pragma unroll
        for (int q = 0; q < 4; q++) {
            float4 v;
            v.x = f2lo(acc[i][2 * q])     + bq[q].x;
            v.y = f2hi(acc[i][2 * q])     + bq[q].y;
            v.z = f2lo(acc[i][2 * q + 1]) + bq[q].z;
            v.w = f2hi(acc[i][2 * q + 1]) + bq[q].w;
            *(float4*)(rp + 64 * q) = v;
        }
    }
}

// ---------------------------------------------------------------------------
// Recurrence: 128 CTAs x 512 threads. CTA = (dir, 8 h-columns).
// NEW: chunked h-staging overlapped with phase 1 —
//   stage k[0,256) (all threads); sync;
//   warps 0-7 (ks<4) compute while warps 8-15 stage k[256,512); sync;
//   warps 8-15 compute; sync; phase 2.
// Grid barrier: atomicAdd arrival + last-arriver release (padded lines).
// smem floats: Ws[24][520] | Hs[512][32] | Red[24][264] | Bh[24]
// ---------------------------------------------------------------------------
#define REC_SMEM_FLOATS 35232
#define REC_SMEM_BYTES  (REC_SMEM_FLOATS * 4)
#define WS_OFF  0
#define HS_OFF  12480
#define RED_OFF 28864
#define BH_OFF  35200

__device__ __forceinline__ void rec_phase1(
    const float* __restrict__ hb,
    const float* __restrict__ w0, const float* __restrict__ w1,
    const float* __restrict__ w2,
    float* __restrict__ rp0, float* __restrict__ rp1, float* __restrict__ rp2)
{
    u64 a0x = 0ull, a0y = 0ull, a1x = 0ull, a1y = 0ull, a2x = 0ull, a2y = 0ull;
#pragma unroll 4
    for (int kk = 0; kk < 64; kk += 4) {
        ulonglong2 h0 = *(const ulonglong2*)(hb + ((kk + 0) << 5));
        ulonglong2 h1 = *(const ulonglong2*)(hb + ((kk + 1) << 5));
        ulonglong2 h2 = *(const ulonglong2*)(hb + ((kk + 2) << 5));
        ulonglong2 h3 = *(const ulonglong2*)(hb + ((kk + 3) << 5));
        float4 wr = *(const float4*)(w0 + kk);
        float4 wz = *(const float4*)(w1 + kk);
        float4 wn = *(const float4*)(w2 + kk);
        u64 p;
        p = pk(wr.x); FFMA2(a0x, h0.x, p); FFMA2(a0y, h0.y, p);
        p = pk(wr.y); FFMA2(a0x, h1.x, p); FFMA2(a0y, h1.y, p);
        p = pk(wr.z); FFMA2(a0x, h2.x, p); FFMA2(a0y, h2.y, p);
        p = pk(wr.w); FFMA2(a0x, h3.x, p); FFMA2(a0y, h3.y, p);
        p = pk(wz.x); FFMA2(a1x, h0.x, p); FFMA2(a1y, h0.y, p);
        p = pk(wz.y); FFMA2(a1x, h1.x, p); FFMA2(a1y, h1.y, p);
        p = pk(wz.z); FFMA2(a1x, h2.x, p); FFMA2(a1y, h2.y, p);
        p = pk(wz.w); FFMA2(a1x, h3.x, p); FFMA2(a1y, h3.y, p);
        p = pk(wn.x); FFMA2(a2x, h0.x, p); FFMA2(a2y, h0.y, p);
        p = pk(wn.y); FFMA2(a2x, h1.x, p); FFMA2(a2y, h1.y, p);
        p = pk(wn.z); FFMA2(a2x, h2.x, p); FFMA2(a2y, h2.y, p);
        p = pk(wn.w); FFMA2(a2x, h3.x, p); FFMA2(a2y, h3.y, p);
    }
    *(u64*)(rp0) = a0x; *(u64*)(rp0 + 2) = a0y;
    *(u64*)(rp1) = a1x; *(u64*)(rp1 + 2) = a1y;
    *(u64*)(rp2) = a2x; *(u64*)(rp2 + 2) = a2y;
}

__global__ __launch_bounds__(512, 1) void gru_rec(
    const float* __restrict__ whh,    // [2][1536][512]
    const float* __restrict__ bhh)    // [2][1536]
{
    extern __shared__ float sm[];
    float* Ws  = sm + WS_OFF;         // [24][520] padded rows
    float* Hs  = sm + HS_OFF;         // [512][32] h_prev, k-major
    float* Red = sm + RED_OFF;        // [24][264] padded
    float* Bh  = sm + BH_OFF;         // [24]

    const int tid = threadIdx.x;
    const int dir = blockIdx.x >> 6;
    const int cb  = blockIdx.x & 63;

    const float* wbase = whh + dir * (1536 * 512);
#pragma unroll
    for (int i = 0; i < 6; i++) {
        int idx4 = tid + i * 512;           // 0..3071 (float4 index)
        int row  = idx4 >> 7;               // 0..23  (g*8 + cl)
        int k4   = idx4 & 127;
        int g = row >> 3, cl = row & 7;
        float4 v = *(const float4*)(wbase + ((g << 9) + cb * 8 + cl) * 512 + k4 * 4);
        *(float4*)(Ws + row * 520 + k4 * 4) = v;
    }
    if (tid < 24) {
        int g = tid >> 3, cl = tid & 7;
        Bh[tid] = bhh[dir * 1536 + (g << 9) + cb * 8 + cl];
    }
    __syncthreads();

    const int ks = tid >> 6;            // 0..7  k-eighth (phase 1)
    const int rr = tid & 63;
    const int c  = rr >> 3;             // 0..7  column
    const int bg = rr & 7;              // 0..7  batch quad
    const int k0 = ks << 6;

    const int c2 = tid >> 5;            // 0..7  (phase 2, tid<256)
    const int b2 = tid & 31;

    const float* xgb = g_xg + dir * XG_DIR;
    float*       yb  = g_y  + dir * Y_DIR;

    const float* w0 = Ws + (0 * 8 + c) * 520 + k0;    // r gate row
    const float* w1 = Ws + (1 * 8 + c) * 520 + k0;    // z gate row
    const float* w2 = Ws + (2 * 8 + c) * 520 + k0;    // n gate row
    const float* hb = Hs + (k0 << 5) + (bg << 2);
    float* rp0 = Red + (0 * 8 + c) * 264 + (ks << 5) + (bg << 2);
    float* rp1 = Red + (1 * 8 + c) * 264 + (ks << 5) + (bg << 2);
    float* rp2 = Red + (2 * 8 + c) * 264 + (ks << 5) + (bg << 2);

    float bhr = 0.f, bhz = 0.f, bhn = 0.f;
    if (tid < 256) {
        bhr = Bh[c2]; bhz = Bh[8 + c2]; bhn = Bh[16 + c2];
    }

    for (int step = 0; step < 512; step++) {
        const int tt = dir ? (511 - step) : step;
        const int tp = dir ? (tt + 1) : (tt - 1);
        const float* hsrc = yb + tp * 16384;

        // xg prefetch for phase 2 (hidden under staging + phase 1)
        float xr = 0.f, xz = 0.f, xn = 0.f;
        if (tid < 256) {
            const float* xp = xgb + (tt * 32 + b2) * 1536 + cb * 8 + c2;
            xr = __ldg(xp); xz = __ldg(xp + 512); xn = __ldg(xp + 1024);
        }

        // stage chunk 0: h_prev k[0,256) -> Hs floats [0, 8192)  (all threads)
        if (step == 0) {
#pragma unroll
            for (int i = 0; i < 4; i++)
                *(float4*)(Hs + ((tid + i * 512) << 2)) = make_float4(0.f, 0.f, 0.f, 0.f);
        } else {
#pragma unroll
            for (int i = 0; i < 4; i++) {
                int idx = (tid + i * 512) << 2;
                *(float4*)(Hs + idx) = __ldcg((const float4*)(hsrc + idx));
            }
        }
        __syncthreads();

        // half A: warps 0-7 compute on chunk 0; warps 8-15 stage chunk 1
        if (tid < 256) {
            rec_phase1(hb, w0, w1, w2, rp0, rp1, rp2);
        } else {
            const int t2 = tid - 256;
            if (step == 0) {
#pragma unroll
                for (int j = 0; j < 8; j++)
                    *(float4*)(Hs + 8192 + ((t2 + j * 256) << 2)) =
                        make_float4(0.f, 0.f, 0.f, 0.f);
            } else {
#pragma unroll
                for (int j = 0; j < 8; j++) {
                    int idx = 8192 + ((t2 + j * 256) << 2);
                    *(float4*)(Hs + idx) = __ldcg((const float4*)(hsrc + idx));
                }
            }
        }
        __syncthreads();

        // half B: warps 8-15 compute on chunk 1
        if (tid >= 256)
            rec_phase1(hb, w0, w1, w2, rp0, rp1, rp2);
        __syncthreads();

        // phase 2: thread (c2, b2) reduces 8 k-partials and applies gates
        if (tid < 256) {
            float s[3];
#pragma unroll
            for (int g = 0; g < 3; g++) {
                const float* rp = Red + ((g << 3) + c2) * 264 + b2;
                float t0 = rp[0]   + rp[32],  t1 = rp[64]  + rp[96];
                float t2 = rp[128] + rp[160], t3 = rp[192] + rp[224];
                s[g] = (t0 + t1) + (t2 + t3);
            }
            const float hp = Hs[(((cb << 3) + c2) << 5) + b2];   // 0 at step 0
            const float r = 1.f / (1.f + expf(-(xr + s[0] + bhr)));
            const float z = 1.f / (1.f + expf(-(xz + s[1] + bhz)));
            const float n = tanhf(xn + r * (s[2] + bhn));
            yb[tt * 16384 + (((cb << 3) + c2) << 5) + b2] = (1.f - z) * n + z * hp;
        }

        // ---- grid barrier: atomic arrival + last-arriver release ----
        __syncthreads();                         // all y stores issued
        const unsigned tgt = (unsigned)step + 1u;
        if (tid == 0) {
            __threadfence();                     // y visible before arrival
            unsigned old = atomicAdd(&g_cnt[dir * 32], 1u);
            if (old == ((unsigned)step << 6) + 63u) {
                g_relp[dir * 32] = tgt;          // completer releases directly
            } else {
                while ((int)(g_relp[dir * 32] - tgt) < 0) { }
            }
            __threadfence();                     // acquire
        }
        __syncthreads();
    }
}

// ---------------------------------------------------------------------------
// BatchNorm (training-mode batch stats), folded to scale/shift
// ---------------------------------------------------------------------------
__global__ void bn_zero()
{
    int t = threadIdx.x;                      // 1024 threads
    g_sum[t] = 0.f;
    g_sqs[t] = 0.f;
}

__global__ void bar_init()
{
    int t = threadIdx.x;                      // 64 threads
    g_cnt[t] = 0u;
    g_relp[t] = 0u;
}

__global__ __launch_bounds__(256) void bn_stats()
{
    const int ch = blockIdx.x;
    const int dir = ch >> 9, c = ch & 511;
    const float* p = g_y + dir * Y_DIR + c * 32;
    float s = 0.f, q = 0.f;
#pragma unroll 4
    for (int i = threadIdx.x; i < 512 * 32; i += 256) {
        int t = i >> 5, b = i & 31;
        float v = p[t * 16384 + b];
        s += v; q += v * v;
    }
#pragma unroll
    for (int o = 16; o > 0; o >>= 1) {
        s += __shfl_down_sync(0xFFFFFFFFu, s, o);
        q += __shfl_down_sync(0xFFFFFFFFu, q, o);
    }
    if ((threadIdx.x & 31) == 0) {
        atomicAdd(&g_sum[ch], s);
        atomicAdd(&g_sqs[ch], q);
    }
}

__global__ void bn_finalize(const float* __restrict__ gamma,
                            const float* __restrict__ beta)
{
    int c = threadIdx.x;                      // 1024 threads
    float mean = g_sum[c] * (1.f / 16384.f);
    float var  = g_sqs[c] * (1.f / 16384.f) - mean * mean;
    float sc   = gamma[c] * rsqrtf(var + 1e-5f);
    g_scale[c] = sc;
    g_shift[c] = beta[c] - mean * sc;
}

__global__ __launch_bounds__(256) void bn_apply(float* __restrict__ out, int last)
{
    __shared__ float tile[256 * 33];
    const int bi   = blockIdx.x;              // t(512) x dir(2) x half(2)
    const int t    = bi >> 2;
    const int dir  = (bi >> 1) & 1;
    const int half = bi & 1;

    const float* src = g_y + dir * Y_DIR + t * 16384 + half * 256 * 32;
    for (int i = threadIdx.x; i < 8192; i += 256) {
        int c = i >> 5, b = i & 31;
        tile[c * 33 + b] = src[c * 32 + b];
    }
    __syncthreads();

    float* dst = last ? out : g_xin;
    const int chb = dir * 512 + half * 256;
    for (int i = threadIdx.x; i < 8192; i += 256) {
        int b = i >> 8, c = i & 255;
        int ch = chb + c;
        dst[(size_t)(b * 512 + t) * 1024 + ch] =
            tile[c * 33 + b] * g_scale[ch] + g_shift[ch];
    }
}

// ---------------------------------------------------------------------------
extern "C" void kernel_launch(void* const* d_in, const int* in_sizes, int n_in,
                              void* d_out, int out_size)
{
    const float* x         = (const float*)d_in[0];   // [32][512][1280]
    const float* w_ih0     = (const float*)d_in[1];   // [2][1536][1280]
    const float* w_hh0     = (const float*)d_in[2];   // [2][1536][512]
    const float* b_ih0     = (const float*)d_in[3];   // [2][1536]
    const float* b_hh0     = (const float*)d_in[4];   // [2][1536]
    const float* w_ih_rest = (const float*)d_in[5];   // [2][2][1536][1024]
    const float* w_hh_rest = (const float*)d_in[6];   // [2][2][1536][512]
    const float* b_ih_rest = (const float*)d_in[7];   // [2][2][1536]
    const float* b_hh_rest = (const float*)d_in[8];   // [2][2][1536]
    const float* gamma     = (const float*)d_in[9];   // [3][1024]
    const float* beta      = (const float*)d_in[10];  // [3][1024]
    float* out = (float*)d_out;                       // [32][512][1024]

    static int attr_set = 0;
    if (!attr_set) {
        cudaFuncSetAttribute(gru_rec, cudaFuncAttributeMaxDynamicSharedMemorySize,
                             REC_SMEM_BYTES);
        attr_set = 1;
    }

    for (int l = 0; l < 3; l++) {
        const float* A   = (l == 0) ? x : nullptr;    // nullptr -> g_xin
        const int    K   = (l == 0) ? 1280 : 1024;
        const float* Wih = (l == 0) ? w_ih0 : w_ih_rest + (size_t)(l - 1) * 2 * 1536 * 1024;
        const float* Bih = (l == 0) ? b_ih0 : b_ih_rest + (l - 1) * 3072;
        const float* Whh = (l == 0) ? w_hh0 : w_hh_rest + (size_t)(l - 1) * 2 * 1536 * 512;
        const float* Bhh = (l == 0) ? b_hh0 : b_hh_rest + (l - 1) * 3072;

        bn_zero<<<1, 1024>>>();
        bar_init<<<1, 64>>>();
        gemm_xg<<<dim3(12, 128), 256>>>(A, Wih, Bih, K);
        gru_rec<<<128, 512, REC_SMEM_BYTES>>>(Whh, Bhh);      // ncu ordinal #4
        bn_stats<<<1024, 256>>>();
        bn_finalize<<<1, 1024>>>(gamma + l * 1024, beta + l * 1024);
        bn_apply<<<2048, 256>>>(out, (l == 2) ? 1 : 0);
    }
}

// round 17
// speedup vs baseline: 1.3089x; 1.1768x over previous
#include <cuda_runtime.h>
#include <math.h>

// B=32, T=512, F=1280, H=512, L=3. 3H=1536, 2H=1024. M=B*T=16384.
//
// NOTE (R11): compute_103 PTX => NO tcgen05. mma.sync/ldmatrix (sm_80 PTX)
//             assemble fine -> HMMA fallback tensor path.
// NOTE (R16): NEVER pass __device__ globals as kernel args from host code
//             (host shadow symbol != device address). Reference them in
//             device code only.
//
// Input projections on mma.sync bf16 with 3-term hi/lo split:
//   A*W ~= Ah*Wh + Al*Wh + Ah*Wl   (residual ~1e-5 rel, threshold 1e-3)
//
// Layouts:
//   xg   [dir][t*32+b][1536]        (input projections, gate-major r/z/n)
//   y    [dir][t][c][b] (512x512x32) transposed hidden outputs
//   xin  [b*512+t][1024]            next-layer input / final output layout
//
// Launch order per layer: conv_a, conv_w, initk, gemm_mma(#4 = ncu ordinal),
// gru, stats, finalize, apply.

#define XG_DIR 25165824   // 512*32*1536
#define Y_DIR   8388608   // 512*512*32

typedef unsigned long long u64;

#define FFMA2(c, a, b) asm("fma.rn.f32x2 %0, %1, %2, %0;" : "+l"(c) : "l"(a), "l"(b))

__device__ __forceinline__ u64 pk(float x) {
    u64 r; unsigned u = __float_as_uint(x);
    asm("mov.b64 %0, {%1, %1};" : "=l"(r) : "r"(u));
    return r;
}

// ---------------- scratch (device globals; no allocation allowed) ----------
__device__ float g_xg[2 * XG_DIR];        // 201 MB
__device__ float g_y [2 * Y_DIR];         //  67 MB
__device__ float g_xin[32 * 512 * 1024];  //  67 MB
__device__ float g_scale[1024];
__device__ float g_shift[1024];
__device__ float g_sum[1024];
__device__ float g_sqs[1024];
__device__ unsigned g_cnt[64];            // arrival counters: [dir*32] used
__device__ volatile unsigned g_relp[64];  // release words:    [dir*32] used
// bf16 hi/lo split buffers (element i = ushort i)
__device__ uint2 g_ah[16384 * 1280 / 4];  // 42 MB
__device__ uint2 g_al[16384 * 1280 / 4];  // 42 MB
__device__ uint2 g_wh[3072 * 1280 / 4];   // 7.9 MB
__device__ uint2 g_wl[3072 * 1280 / 4];   // 7.9 MB

// ---------------------------------------------------------------------------
// fp32 -> (hi, lo) bf16 split. Globals referenced in DEVICE code only.
// ---------------------------------------------------------------------------
__device__ __forceinline__ unsigned cvt_bf2(float lo, float hi) {
    unsigned r;
    asm("cvt.rn.bf16x2.f32 %0, %1, %2;" : "=r"(r) : "f"(hi), "f"(lo));
    return r;
}

__device__ __forceinline__ void split4(float4 v, unsigned* ph, unsigned* pl) {
    unsigned ph01 = cvt_bf2(v.x, v.y);
    unsigned ph23 = cvt_bf2(v.z, v.w);
    float h0 = __uint_as_float(ph01 << 16);
    float h1 = __uint_as_float(ph01 & 0xFFFF0000u);
    float h2 = __uint_as_float(ph23 << 16);
    float h3 = __uint_as_float(ph23 & 0xFFFF0000u);
    ph[0] = ph01; ph[1] = ph23;
    pl[0] = cvt_bf2(v.x - h0, v.y - h1);
    pl[1] = cvt_bf2(v.z - h2, v.w - h3);
}

__global__ __launch_bounds__(256) void conv_a(
    const float* __restrict__ srcp,   // nullptr -> g_xin
    int n4)
{
    const float* src = srcp ? srcp : g_xin;
    int idx = blockIdx.x * 256 + threadIdx.x;
    if (idx >= n4) return;
    float4 v = ((const float4*)src)[idx];
    unsigned ph[2], pl[2];
    split4(v, ph, pl);
    g_ah[idx] = make_uint2(ph[0], ph[1]);
    g_al[idx] = make_uint2(pl[0], pl[1]);
}

__global__ __launch_bounds__(256) void conv_w(
    const float* __restrict__ srcp,
    int n4)
{
    int idx = blockIdx.x * 256 + threadIdx.x;
    if (idx >= n4) return;
    float4 v = ((const float4*)srcp)[idx];
    unsigned ph[2], pl[2];
    split4(v, ph, pl);
    g_wh[idx] = make_uint2(ph[0], ph[1]);
    g_wl[idx] = make_uint2(pl[0], pl[1]);
}

// per-layer state init (BN accumulators + grid-barrier counters)
__global__ void initk()
{
    int t = threadIdx.x;                  // 1024 threads
    g_sum[t] = 0.f;
    g_sqs[t] = 0.f;
    if (t < 64) { g_cnt[t] = 0u; g_relp[t] = 0u; }
}

// ---------------------------------------------------------------------------
// Tensor-core GEMM: xg[m][n] = sum_k A[m][k] W[n][k] + bias[n]
// mma.sync m16n8k16 bf16, 3-term split. CTA 128M x 128N, 8 warps (32M x 64N).
// smem: 4 x [128][40] bf16 (K32 chunk, pitch 40 halves = conflict-free).
// ---------------------------------------------------------------------------
#define GP 40   // smem pitch in halves

#define LDSM4(r0, r1, r2, r3, addr)                                         \
    asm volatile("ldmatrix.sync.aligned.m8n8.x4.shared.b16 {%0,%1,%2,%3}, [%4];" \
        : "=r"(r0), "=r"(r1), "=r"(r2), "=r"(r3) : "r"(addr) : "memory")

#define MMA16816(d, a, b)                                                   \
    asm("mma.sync.aligned.m16n8k16.row.col.f32.bf16.bf16.f32 "              \
        "{%0,%1,%2,%3}, {%4,%5,%6,%7}, {%8,%9}, {%0,%1,%2,%3};"             \
        : "+f"((d)[0]), "+f"((d)[1]), "+f"((d)[2]), "+f"((d)[3])            \
        : "r"((a)[0]), "r"((a)[1]), "r"((a)[2]), "r"((a)[3]),               \
          "r"((b)[0]), "r"((b)[1]))

__global__ __launch_bounds__(256) void gemm_mma(
    const float* __restrict__ bias,   // [3072]
    int K)
{
    __shared__ __align__(16) unsigned short sAh[128 * GP];
    __shared__ __align__(16) unsigned short sAl[128 * GP];
    __shared__ __align__(16) unsigned short sWh[128 * GP];
    __shared__ __align__(16) unsigned short sWl[128 * GP];

    const int tid  = threadIdx.x;
    const int lane = tid & 31;
    const int wid  = tid >> 5;
    const int wm   = wid >> 1;        // 0..3: warp M offset /32
    const int wn   = wid & 1;         // 0..1: warp N offset /64
    const int bn   = blockIdx.x;      // 0..23 (128-col tiles; 12 per dir)
    const int bm   = blockIdx.y;      // 0..127

    const unsigned short* Ah = (const unsigned short*)g_ah;
    const unsigned short* Al = (const unsigned short*)g_al;
    const unsigned short* Wh = (const unsigned short*)g_wh;
    const unsigned short* Wl = (const unsigned short*)g_wl;

    const unsigned sah = (unsigned)__cvta_generic_to_shared(sAh);
    const unsigned sal = (unsigned)__cvta_generic_to_shared(sAl);
    const unsigned swh = (unsigned)__cvta_generic_to_shared(sWh);
    const unsigned swl = (unsigned)__cvta_generic_to_shared(sWl);

    // ldmatrix per-lane offsets (in halves, within current chunk)
    const int l16 = lane & 15, lhi = lane >> 4;
    const int aoff0 = (wm * 32 + l16) * GP + lhi * 8;          // A tile 0
    const int aoff1 = aoff0 + 16 * GP;                         // A tile 1
    const int bg = lane >> 3, blr = lane & 7;
    const int bnrow = ((bg >> 1) << 3) + blr;                  // n within 16
    const int bkoff = (bg & 1) << 3;                           // k 0 or 8
    int boff[4];
#pragma unroll
    for (int p = 0; p < 4; p++)
        boff[p] = (wn * 64 + p * 16 + bnrow) * GP + bkoff;

    float acc[2][8][4];
#pragma unroll
    for (int mt = 0; mt < 2; mt++)
#pragma unroll
        for (int nt = 0; nt < 8; nt++)
#pragma unroll
            for (int q = 0; q < 4; q++) acc[mt][nt][q] = 0.f;

    for (int kt = 0; kt < K; kt += 32) {
        // stage K32 chunk: 4 arrays, each 128 rows x 32 halves
#pragma unroll
        for (int i = 0; i < 4; i++) {
            int idx = tid + (i << 8);          // 0..1023
            int row = idx >> 3;
            int c4  = (idx & 7) << 2;          // halves
            size_t goffA = (size_t)(bm * 128 + row) * K + kt + c4;
            size_t goffW = (size_t)(bn * 128 + row) * K + kt + c4;
            *(uint2*)&sAh[row * GP + c4] = *(const uint2*)(Ah + goffA);
            *(uint2*)&sAl[row * GP + c4] = *(const uint2*)(Al + goffA);
            *(uint2*)&sWh[row * GP + c4] = *(const uint2*)(Wh + goffW);
            *(uint2*)&sWl[row * GP + c4] = *(const uint2*)(Wl + goffW);
        }
        __syncthreads();

#pragma unroll
        for (int k16o = 0; k16o < 32; k16o += 16) {
            unsigned ah0[4], ah1[4], al0[4], al1[4];
            unsigned bh[8][2], bl[8][2];
            LDSM4(ah0[0], ah0[1], ah0[2], ah0[3], sah + ((aoff0 + k16o) << 1));
            LDSM4(ah1[0], ah1[1], ah1[2], ah1[3], sah + ((aoff1 + k16o) << 1));
            LDSM4(al0[0], al0[1], al0[2], al0[3], sal + ((aoff0 + k16o) << 1));
            LDSM4(al1[0], al1[1], al1[2], al1[3], sal + ((aoff1 + k16o) << 1));
#pragma unroll
            for (int p = 0; p < 4; p++) {
                LDSM4(bh[2 * p][0], bh[2 * p][1], bh[2 * p + 1][0], bh[2 * p + 1][1],
                      swh + ((boff[p] + k16o) << 1));
                LDSM4(bl[2 * p][0], bl[2 * p][1], bl[2 * p + 1][0], bl[2 * p + 1][1],
                      swl + ((boff[p] + k16o) << 1));
            }
#pragma unroll
            for (int nt = 0; nt < 8; nt++) {
                MMA16816(acc[0][nt], ah0, bh[nt]);
                MMA16816(acc[1][nt], ah1, bh[nt]);
                MMA16816(acc[0][nt], al0, bh[nt]);
                MMA16816(acc[1][nt], al1, bh[nt]);
                MMA16816(acc[0][nt], ah0, bl[nt]);
                MMA16816(acc[1][nt], ah1, bl[nt]);
            }
        }
        __syncthreads();
    }

    // Epilogue: + bias, scatter to xg[dir][t*32+b][g]
    const int dir = (bn >= 12);
    float* xgb = g_xg + dir * XG_DIR;
#pragma unroll
    for (int nt = 0; nt < 8; nt++) {
        int ng = bn * 128 + wn * 64 + nt * 8 + ((lane & 3) << 1);  // global n
        float b0 = bias[ng], b1 = bias[ng + 1];
        int nl = ng - dir * 1536;
#pragma unroll
        for (int mt = 0; mt < 2; mt++) {
            int m0 = bm * 128 + wm * 32 + mt * 16 + (lane >> 2);
            int bb = m0 >> 9, tt = m0 & 511;
            *(float2*)(xgb + (tt * 32 + bb) * 1536 + nl) =
                make_float2(acc[mt][nt][0] + b0, acc[mt][nt][1] + b1);
            int m1 = m0 + 8;
            bb = m1 >> 9; tt = m1 & 511;
            *(float2*)(xgb + (tt * 32 + bb) * 1536 + nl) =
                make_float2(acc[mt][nt][2] + b0, acc[mt][nt][3] + b1);
        }
    }
}

// ---------------------------------------------------------------------------
// Recurrence (R13 frozen): 128 CTAs x 512 threads. CTA = (dir, 8 h-columns).
// Grid barrier: atomicAdd arrival + last-arriver release (padded lines).
// smem floats: Ws[24][520] | Hs[512][32] | Red[24][264] | Bh[24]
// ---------------------------------------------------------------------------
#define REC_SMEM_FLOATS 35232
#define REC_SMEM_BYTES  (REC_SMEM_FLOATS * 4)
#define WS_OFF  0
#define HS_OFF  12480
#define RED_OFF 28864
#define BH_OFF  35200

__global__ __launch_bounds__(512, 1) void gru_rec(
    const float* __restrict__ whh,    // [2][1536][512]
    const float* __restrict__ bhh)    // [2][1536]
{
    extern __shared__ float sm[];
    float* Ws  = sm + WS_OFF;         // [24][520] padded rows
    float* Hs  = sm + HS_OFF;         // [512][32] h_prev, k-major
    float* Red = sm + RED_OFF;        // [24][264] padded
    float* Bh  = sm + BH_OFF;         // [24]

    const int tid = threadIdx.x;
    const int dir = blockIdx.x >> 6;
    const int cb  = blockIdx.x & 63;

    const float* wbase = whh + dir * (1536 * 512);
#pragma unroll
    for (int i = 0; i < 6; i++) {
        int idx4 = tid + i * 512;           // 0..3071 (float4 index)
        int row  = idx4 >> 7;               // 0..23  (g*8 + cl)
        int k4   = idx4 & 127;
        int g = row >> 3, cl = row & 7;
        float4 v = *(const float4*)(wbase + ((g << 9) + cb * 8 + cl) * 512 + k4 * 4);
        *(float4*)(Ws + row * 520 + k4 * 4) = v;
    }
    if (tid < 24) {
        int g = tid >> 3, cl = tid & 7;
        Bh[tid] = bhh[dir * 1536 + (g << 9) + cb * 8 + cl];
    }
    __syncthreads();

    const int ks = tid >> 6;            // 0..7  k-eighth (phase 1)
    const int rr = tid & 63;
    const int c  = rr >> 3;             // 0..7  column
    const int bg = rr & 7;              // 0..7  batch quad
    const int k0 = ks << 6;

    const int c2 = tid >> 5;            // 0..7  (phase 2, tid<256)
    const int b2 = tid & 31;

    const float* xgb = g_xg + dir * XG_DIR;
    float*       yb  = g_y  + dir * Y_DIR;

    const float* w0 = Ws + (0 * 8 + c) * 520 + k0;    // r gate row
    const float* w1 = Ws + (1 * 8 + c) * 520 + k0;    // z gate row
    const float* w2 = Ws + (2 * 8 + c) * 520 + k0;    // n gate row
    const float* hb = Hs + (k0 << 5) + (bg << 2);

    float bhr = 0.f, bhz = 0.f, bhn = 0.f;
    if (tid < 256) {
        bhr = Bh[c2]; bhz = Bh[8 + c2]; bhn = Bh[16 + c2];
    }

    for (int step = 0; step < 512; step++) {
        const int tt = dir ? (511 - step) : step;
        const int tp = dir ? (tt + 1) : (tt - 1);
        const float* hsrc = yb + tp * 16384;

        // xg prefetch for phase 2 (hidden under staging + phase 1)
        float xr = 0.f, xz = 0.f, xn = 0.f;
        if (tid < 256) {
            const float* xp = xgb + (tt * 32 + b2) * 1536 + cb * 8 + c2;
            xr = __ldg(xp); xz = __ldg(xp + 512); xn = __ldg(xp + 1024);
        }

        // stage h_prev into Hs (contiguous 64KB, coalesced)
        if (step == 0) {
#pragma unroll
            for (int i = 0; i < 8; i++)
                *(float4*)(Hs + ((tid + i * 512) << 2)) = make_float4(0.f, 0.f, 0.f, 0.f);
        } else {
#pragma unroll
            for (int i = 0; i < 8; i++) {
                int idx = (tid + i * 512) << 2;
                *(float4*)(Hs + idx) = __ldcg((const float4*)(hsrc + idx));
            }
        }
        __syncthreads();

        // phase 1: 3 gates x 2 batch-pairs over 64 k
        u64 a0x = 0ull, a0y = 0ull, a1x = 0ull, a1y = 0ull, a2x = 0ull, a2y = 0ull;
#pragma unroll 4
        for (int kk = 0; kk < 64; kk += 4) {
            ulonglong2 h0 = *(const ulonglong2*)(hb + ((kk + 0) << 5));
            ulonglong2 h1 = *(const ulonglong2*)(hb + ((kk + 1) << 5));
            ulonglong2 h2 = *(const ulonglong2*)(hb + ((kk + 2) << 5));
            ulonglong2 h3 = *(const ulonglong2*)(hb + ((kk + 3) << 5));
            float4 wr = *(const float4*)(w0 + kk);
            float4 wz = *(const float4*)(w1 + kk);
            float4 wn = *(const float4*)(w2 + kk);
            u64 p;
            p = pk(wr.x); FFMA2(a0x, h0.x, p); FFMA2(a0y, h0.y, p);
            p = pk(wr.y); FFMA2(a0x, h1.x, p); FFMA2(a0y, h1.y, p);
            p = pk(wr.z); FFMA2(a0x, h2.x, p); FFMA2(a0y, h2.y, p);
            p = pk(wr.w); FFMA2(a0x, h3.x, p); FFMA2(a0y, h3.y, p);
            p = pk(wz.x); FFMA2(a1x, h0.x, p); FFMA2(a1y, h0.y, p);
            p = pk(wz.y); FFMA2(a1x, h1.x, p); FFMA2(a1y, h1.y, p);
            p = pk(wz.z); FFMA2(a1x, h2.x, p); FFMA2(a1y, h2.y, p);
            p = pk(wz.w); FFMA2(a1x, h3.x, p); FFMA2(a1y, h3.y, p);
            p = pk(wn.x); FFMA2(a2x, h0.x, p); FFMA2(a2y, h0.y, p);
            p = pk(wn.y); FFMA2(a2x, h1.x, p); FFMA2(a2y, h1.y, p);
            p = pk(wn.z); FFMA2(a2x, h2.x, p); FFMA2(a2y, h2.y, p);
            p = pk(wn.w); FFMA2(a2x, h3.x, p); FFMA2(a2y, h3.y, p);
        }

        // store partials: Red[(g*8 + c)][ks*32 + 4bg + {0..3}]
        {
            float* rp0 = Red + (0 * 8 + c) * 264 + (ks << 5) + (bg << 2);
            float* rp1 = Red + (1 * 8 + c) * 264 + (ks << 5) + (bg << 2);
            float* rp2 = Red + (2 * 8 + c) * 264 + (ks << 5) + (bg << 2);
            *(u64*)(rp0) = a0x; *(u64*)(rp0 + 2) = a0y;
            *(u64*)(rp1) = a1x; *(u64*)(rp1 + 2) = a1y;
            *(u64*)(rp2) = a2x; *(u64*)(rp2 + 2) = a2y;
        }
        __syncthreads();

        // phase 2: thread (c2, b2) reduces 8 k-partials and applies gates
        if (tid < 256) {
            float s[3];
#pragma unroll
            for (int g = 0; g < 3; g++) {
                const float* rp = Red + ((g << 3) + c2) * 264 + b2;
                float t0 = rp[0]   + rp[32],  t1 = rp[64]  + rp[96];
                float t2 = rp[128] + rp[160], t3 = rp[192] + rp[224];
                s[g] = (t0 + t1) + (t2 + t3);
            }
            const float hp = Hs[(((cb << 3) + c2) << 5) + b2];   // 0 at step 0
            const float r = 1.f / (1.f + expf(-(xr + s[0] + bhr)));
            const float z = 1.f / (1.f + expf(-(xz + s[1] + bhz)));
            const float n = tanhf(xn + r * (s[2] + bhn));
            yb[tt * 16384 + (((cb << 3) + c2) << 5) + b2] = (1.f - z) * n + z * hp;
        }

        // ---- grid barrier: atomic arrival + last-arriver release ----
        __syncthreads();                         // all y stores issued
        const unsigned tgt = (unsigned)step + 1u;
        if (tid == 0) {
            __threadfence();                     // y visible before arrival
            unsigned old = atomicAdd(&g_cnt[dir * 32], 1u);
            if (old == ((unsigned)step << 6) + 63u) {
                g_relp[dir * 32] = tgt;          // completer releases directly
            } else {
                while ((int)(g_relp[dir * 32] - tgt) < 0) { }
            }
            __threadfence();                     // acquire
        }
        __syncthreads();
    }
}

// ---------------------------------------------------------------------------
// BatchNorm (training-mode batch stats), folded to scale/shift
// ---------------------------------------------------------------------------
__global__ __launch_bounds__(256) void bn_stats()
{
    const int ch = blockIdx.x;
    const int dir = ch >> 9, c = ch & 511;
    const float* p = g_y + dir * Y_DIR + c * 32;
    float s = 0.f, q = 0.f;
#pragma unroll 4
    for (int i = threadIdx.x; i < 512 * 32; i += 256) {
        int t = i >> 5, b = i & 31;
        float v = p[t * 16384 + b];
        s += v; q += v * v;
    }
#pragma unroll
    for (int o = 16; o > 0; o >>= 1) {
        s += __shfl_down_sync(0xFFFFFFFFu, s, o);
        q += __shfl_down_sync(0xFFFFFFFFu, q, o);
    }
    if ((threadIdx.x & 31) == 0) {
        atomicAdd(&g_sum[ch], s);
        atomicAdd(&g_sqs[ch], q);
    }
}

__global__ void bn_finalize(const float* __restrict__ gamma,
                            const float* __restrict__ beta)
{
    int c = threadIdx.x;                      // 1024 threads
    float mean = g_sum[c] * (1.f / 16384.f);
    float var  = g_sqs[c] * (1.f / 16384.f) - mean * mean;
    float sc   = gamma[c] * rsqrtf(var + 1e-5f);
    g_scale[c] = sc;
    g_shift[c] = beta[c] - mean * sc;
}

__global__ __launch_bounds__(256) void bn_apply(float* __restrict__ out, int last)
{
    __shared__ float tile[256 * 33];
    const int bi   = blockIdx.x;              // t(512) x dir(2) x half(2)
    const int t    = bi >> 2;
    const int dir  = (bi >> 1) & 1;
    const int half = bi & 1;

    const float* src = g_y + dir * Y_DIR + t * 16384 + half * 256 * 32;
    for (int i = threadIdx.x; i < 8192; i += 256) {
        int c = i >> 5, b = i & 31;
        tile[c * 33 + b] = src[c * 32 + b];
    }
    __syncthreads();

    float* dst = last ? out : g_xin;
    const int chb = dir * 512 + half * 256;
    for (int i = threadIdx.x; i < 8192; i += 256) {
        int b = i >> 8, c = i & 255;
        int ch = chb + c;
        dst[(size_t)(b * 512 + t) * 1024 + ch] =
            tile[c * 33 + b] * g_scale[ch] + g_shift[ch];
    }
}

// ---------------------------------------------------------------------------
extern "C" void kernel_launch(void* const* d_in, const int* in_sizes, int n_in,
                              void* d_out, int out_size)
{
    const float* x         = (const float*)d_in[0];   // [32][512][1280]
    const float* w_ih0     = (const float*)d_in[1];   // [2][1536][1280]
    const float* w_hh0     = (const float*)d_in[2];   // [2][1536][512]
    const float* b_ih0     = (const float*)d_in[3];   // [2][1536]
    const float* b_hh0     = (const float*)d_in[4];   // [2][1536]
    const float* w_ih_rest = (const float*)d_in[5];   // [2][2][1536][1024]
    const float* w_hh_rest = (const float*)d_in[6];   // [2][2][1536][512]
    const float* b_ih_rest = (const float*)d_in[7];   // [2][2][1536]
    const float* b_hh_rest = (const float*)d_in[8];   // [2][2][1536]
    const float* gamma     = (const float*)d_in[9];   // [3][1024]
    const float* beta      = (const float*)d_in[10];  // [3][1024]
    float* out = (float*)d_out;                       // [32][512][1024]

    static int attr_set = 0;
    if (!attr_set) {
        cudaFuncSetAttribute(gru_rec, cudaFuncAttributeMaxDynamicSharedMemorySize,
                             REC_SMEM_BYTES);
        attr_set = 1;
    }

    for (int l = 0; l < 3; l++) {
        const float* A   = (l == 0) ? x : nullptr;    // nullptr -> g_xin
        const int    K   = (l == 0) ? 1280 : 1024;
        const float* Wih = (l == 0) ? w_ih0 : w_ih_rest + (size_t)(l - 1) * 2 * 1536 * 1024;
        const float* Bih = (l == 0) ? b_ih0 : b_ih_rest + (l - 1) * 3072;
        const float* Whh = (l == 0) ? w_hh0 : w_hh_rest + (size_t)(l - 1) * 2 * 1536 * 512;
        const float* Bhh = (l == 0) ? b_hh0 : b_hh_rest + (l - 1) * 3072;

        const int mk4 = 16384 * K / 4;
        const int nk4 = 3072 * K / 4;

        conv_a<<<mk4 / 256, 256>>>(A, mk4);
        conv_w<<<nk4 / 256, 256>>>(Wih, nk4);
        initk<<<1, 1024>>>();
        gemm_mma<<<dim3(24, 128), 256>>>(Bih, K);             // ncu ordinal #4
        gru_rec<<<128, 512, REC_SMEM_BYTES>>>(Whh, Bhh);
        bn_stats<<<1024, 256>>>();
        bn_finalize<<<1, 1024>>>(gamma + l * 1024, beta + l * 1024);
        bn_apply<<<2048, 256>>>(out, (l == 2) ? 1 : 0);
    }
}